// round 2
// baseline (speedup 1.0000x reference)
#include <cuda_runtime.h>
#include <cuda_bf16.h>
#include <cstdint>

#define CIN   512
#define CQK   64
#define MTOK  4096

// ---------------- scratch (device globals; no allocations) ----------------
__device__ float d_styleR[4 * CIN * MTOK];     // resized style, (B,C,M)
__device__ float d_f[4 * MTOK * CQK];          // (B,M,64)
__device__ float d_g[4 * MTOK * CQK];          // (B,M,64)
__device__ float d_h[4 * MTOK * CIN];          // (B,M,512)
__device__ float d_S[(size_t)4 * MTOK * MTOK]; // (B,M,N) logits / probs
__device__ float d_ao[4 * MTOK * CIN];         // (B,M,512)

// ---------------- packed f32x2 helpers ----------------
__device__ __forceinline__ void ffma2(unsigned long long &d, unsigned long long a, unsigned long long b) {
    asm("fma.rn.f32x2 %0, %1, %2, %0;" : "+l"(d) : "l"(a), "l"(b));
}
__device__ __forceinline__ unsigned long long bcast2(float x) {
    unsigned long long r; asm("mov.b64 %0, {%1, %1};" : "=l"(r) : "f"(x)); return r;
}
__device__ __forceinline__ float2 unpack2(unsigned long long v) {
    float2 f; asm("mov.b64 {%0, %1}, %2;" : "=f"(f.x), "=f"(f.y) : "l"(v)); return f;
}

// ============================================================================
// 1) bilinear resize style (80x80 -> 64x64), keeps channel-major (B,C,4096)
// ============================================================================
__global__ void resize_kernel(const float* __restrict__ style, float* __restrict__ out) {
    int idx = blockIdx.x * blockDim.x + threadIdx.x;   // B*C*4096 exact
    int m  = idx & 4095;
    int bc = idx >> 12;
    int x = m & 63, y = m >> 6;
    float sx = fmaxf((x + 0.5f) * 1.25f - 0.5f, 0.0f);
    float sy = fmaxf((y + 0.5f) * 1.25f - 0.5f, 0.0f);
    int x0 = min((int)sx, 79), y0 = min((int)sy, 79);
    int x1 = min(x0 + 1, 79),  y1 = min(y0 + 1, 79);
    float wx = sx - (float)x0, wy = sy - (float)y0;
    const float* p = style + (size_t)bc * 6400;
    float a00 = p[y0 * 80 + x0], a01 = p[y0 * 80 + x1];
    float a10 = p[y1 * 80 + x0], a11 = p[y1 * 80 + x1];
    float r0 = a00 + (a01 - a00) * wx;
    float r1 = a10 + (a11 - a10) * wx;
    out[idx] = r0 + (r1 - r0) * wy;
}

// ============================================================================
// 2) projection: out[b][m][o] = sum_c X[b][c][m]*W[o][c] + bias[o]
//    X channel-major (B,512,4096), out row-major (B,M,O). 64x64 tile.
// ============================================================================
__global__ __launch_bounds__(256) void proj_kernel(
    const float* __restrict__ X, const float* __restrict__ W,
    const float* __restrict__ bias, float* __restrict__ out, int O)
{
    __shared__ float Xs[16][64];
    __shared__ float Ws[16][68];
    const int tid = threadIdx.x;
    const int b  = blockIdx.z;
    const int m0 = blockIdx.x * 64, o0 = blockIdx.y * 64;
    const float* Xb = X + (size_t)b * CIN * MTOK;

    const int oi = tid & 15;          // output o = o0 + oi*4 .. +3
    const int mi = tid >> 4;          // output m = m0 + mi*4 .. +3
    const int xr = tid >> 4, xc = (tid & 15) * 4;
    const int wo = tid >> 2, wc = (tid & 3) * 4;

    unsigned long long acc[4][2];
#pragma unroll
    for (int i = 0; i < 4; i++) { acc[i][0] = 0ull; acc[i][1] = 0ull; }

    for (int c0 = 0; c0 < CIN; c0 += 16) {
        __syncthreads();
        *(float4*)&Xs[xr][xc] = *(const float4*)&Xb[(size_t)(c0 + xr) * MTOK + m0 + xc];
        float4 wv = *(const float4*)&W[(size_t)(o0 + wo) * CIN + c0 + wc];
        Ws[wc + 0][wo] = wv.x; Ws[wc + 1][wo] = wv.y;
        Ws[wc + 2][wo] = wv.z; Ws[wc + 3][wo] = wv.w;
        __syncthreads();
#pragma unroll
        for (int c = 0; c < 16; c++) {
            ulonglong2 wp = *(const ulonglong2*)&Ws[c][oi * 4];
#pragma unroll
            for (int i = 0; i < 4; i++) {
                unsigned long long xp = bcast2(Xs[c][mi * 4 + i]);
                ffma2(acc[i][0], wp.x, xp);
                ffma2(acc[i][1], wp.y, xp);
            }
        }
    }
    float b0 = bias[o0 + oi * 4 + 0], b1 = bias[o0 + oi * 4 + 1];
    float b2 = bias[o0 + oi * 4 + 2], b3 = bias[o0 + oi * 4 + 3];
#pragma unroll
    for (int i = 0; i < 4; i++) {
        float2 u0 = unpack2(acc[i][0]);
        float2 u1 = unpack2(acc[i][1]);
        *(float4*)&out[((size_t)b * MTOK + m0 + mi * 4 + i) * O + o0 + oi * 4] =
            make_float4(u0.x + b0, u0.y + b1, u1.x + b2, u1.y + b3);
    }
}

// ============================================================================
// 3) logits: S[b][m][n] = sum_c f[b][m][c]*g[b][n][c]   (K = 64, fully staged)
// ============================================================================
__global__ __launch_bounds__(256) void logits_kernel(
    const float* __restrict__ f, const float* __restrict__ g, float* __restrict__ S)
{
    __shared__ float fs[64][68];
    __shared__ float gs[64][68];
    const int tid = threadIdx.x;
    const int b  = blockIdx.z;
    const int m0 = blockIdx.x * 64, n0 = blockIdx.y * 64;
    const float* fb = f + ((size_t)b * MTOK + m0) * CQK;
    const float* gb = g + ((size_t)b * MTOK + n0) * CQK;

#pragma unroll
    for (int kk = 0; kk < 4; kk++) {
        int idx = tid + kk * 256;
        int r = idx >> 4, c4 = (idx & 15) * 4;
        float4 fv = *(const float4*)&fb[r * CQK + c4];
        fs[c4 + 0][r] = fv.x; fs[c4 + 1][r] = fv.y; fs[c4 + 2][r] = fv.z; fs[c4 + 3][r] = fv.w;
        float4 gv = *(const float4*)&gb[r * CQK + c4];
        gs[c4 + 0][r] = gv.x; gs[c4 + 1][r] = gv.y; gs[c4 + 2][r] = gv.z; gs[c4 + 3][r] = gv.w;
    }
    __syncthreads();

    const int ni = tid & 15, mi = tid >> 4;
    unsigned long long acc[4][2];
#pragma unroll
    for (int i = 0; i < 4; i++) { acc[i][0] = 0ull; acc[i][1] = 0ull; }

#pragma unroll
    for (int c = 0; c < 64; c++) {
        ulonglong2 gp = *(const ulonglong2*)&gs[c][ni * 4];
#pragma unroll
        for (int i = 0; i < 4; i++) {
            unsigned long long fp = bcast2(fs[c][mi * 4 + i]);
            ffma2(acc[i][0], gp.x, fp);
            ffma2(acc[i][1], gp.y, fp);
        }
    }
#pragma unroll
    for (int i = 0; i < 4; i++) {
        float2 u0 = unpack2(acc[i][0]);
        float2 u1 = unpack2(acc[i][1]);
        *(float4*)&S[((size_t)(b * MTOK) + m0 + mi * 4 + i) * MTOK + n0 + ni * 4] =
            make_float4(u0.x, u0.y, u1.x, u1.y);
    }
}

// ============================================================================
// 4) row softmax over S (rows of 4096), one CTA per row
// ============================================================================
__global__ __launch_bounds__(256) void softmax_kernel(float* __restrict__ S) {
    float4* p = (float4*)(S + (size_t)blockIdx.x * MTOK);
    const int tid = threadIdx.x;
    float4 v[4];
#pragma unroll
    for (int k = 0; k < 4; k++) v[k] = p[tid + k * 256];

    float mx = -1e30f;
#pragma unroll
    for (int k = 0; k < 4; k++)
        mx = fmaxf(mx, fmaxf(fmaxf(v[k].x, v[k].y), fmaxf(v[k].z, v[k].w)));
#pragma unroll
    for (int off = 16; off; off >>= 1) mx = fmaxf(mx, __shfl_xor_sync(~0u, mx, off));
    __shared__ float rs[8];
    if ((tid & 31) == 0) rs[tid >> 5] = mx;
    __syncthreads();
    mx = rs[0];
#pragma unroll
    for (int k = 1; k < 8; k++) mx = fmaxf(mx, rs[k]);
    __syncthreads();

    float s = 0.0f;
#pragma unroll
    for (int k = 0; k < 4; k++) {
        v[k].x = __expf(v[k].x - mx); v[k].y = __expf(v[k].y - mx);
        v[k].z = __expf(v[k].z - mx); v[k].w = __expf(v[k].w - mx);
        s += (v[k].x + v[k].y) + (v[k].z + v[k].w);
    }
#pragma unroll
    for (int off = 16; off; off >>= 1) s += __shfl_xor_sync(~0u, s, off);
    if ((tid & 31) == 0) rs[tid >> 5] = s;
    __syncthreads();
    s = rs[0];
#pragma unroll
    for (int k = 1; k < 8; k++) s += rs[k];
    float inv = 1.0f / s;
#pragma unroll
    for (int k = 0; k < 4; k++) {
        v[k].x *= inv; v[k].y *= inv; v[k].z *= inv; v[k].w *= inv;
        p[tid + k * 256] = v[k];
    }
}

// ============================================================================
// 5) PV GEMM: ao[b][m][c] = sum_n P[b][m][n] * h[b][n][c]
//    128x128 CTA tile, 8x8 thread tile, all f32x2. The dominant kernel.
// ============================================================================
__global__ __launch_bounds__(256, 2) void pv_kernel(
    const float* __restrict__ P, const float* __restrict__ H, float* __restrict__ out)
{
    __shared__ float Ps[16][132];
    __shared__ float Hs[16][132];
    const int tid = threadIdx.x;
    const int b  = blockIdx.z;
    const int m0 = blockIdx.x * 128, c0 = blockIdx.y * 128;
    const float* Pb = P + ((size_t)b * MTOK + m0) * MTOK;
    const float* Hb = H + (size_t)b * MTOK * CIN + c0;
    const int mg = tid >> 4, cg = tid & 15;   // 8 m x 8 c per thread

    unsigned long long acc[8][4];
#pragma unroll
    for (int i = 0; i < 8; i++)
#pragma unroll
        for (int q = 0; q < 4; q++) acc[i][q] = 0ull;

    const int pr = tid >> 2, pc4 = (tid & 3) * 4;          // P loader
    const int hr = tid >> 5, hc4 = (tid & 31) * 4;         // H loader

    for (int n0 = 0; n0 < MTOK; n0 += 16) {
        __syncthreads();
#pragma unroll
        for (int j = 0; j < 2; j++) {
            int r = pr + j * 64;
            float4 v = *(const float4*)&Pb[(size_t)r * MTOK + n0 + pc4];
            Ps[pc4 + 0][r] = v.x; Ps[pc4 + 1][r] = v.y;
            Ps[pc4 + 2][r] = v.z; Ps[pc4 + 3][r] = v.w;
            int kn = hr + j * 8;
            *(float4*)&Hs[kn][hc4] = *(const float4*)&Hb[(size_t)(n0 + kn) * CIN + hc4];
        }
        __syncthreads();
#pragma unroll
        for (int k = 0; k < 16; k++) {
            float4 a0 = *(const float4*)&Ps[k][mg * 8];
            float4 a1 = *(const float4*)&Ps[k][mg * 8 + 4];
            ulonglong2 b0 = *(const ulonglong2*)&Hs[k][cg * 8];
            ulonglong2 b1 = *(const ulonglong2*)&Hs[k][cg * 8 + 4];
            float av[8] = {a0.x, a0.y, a0.z, a0.w, a1.x, a1.y, a1.z, a1.w};
#pragma unroll
            for (int i = 0; i < 8; i++) {
                unsigned long long ap = bcast2(av[i]);
                ffma2(acc[i][0], b0.x, ap);
                ffma2(acc[i][1], b0.y, ap);
                ffma2(acc[i][2], b1.x, ap);
                ffma2(acc[i][3], b1.y, ap);
            }
        }
    }
#pragma unroll
    for (int i = 0; i < 8; i++) {
        float2 u0 = unpack2(acc[i][0]), u1 = unpack2(acc[i][1]);
        float2 u2 = unpack2(acc[i][2]), u3 = unpack2(acc[i][3]);
        float* o = out + ((size_t)b * MTOK + m0 + mg * 8 + i) * CIN + c0 + cg * 8;
        *(float4*)o       = make_float4(u0.x, u0.y, u1.x, u1.y);
        *(float4*)(o + 4) = make_float4(u2.x, u2.y, u3.x, u3.y);
    }
}

// ============================================================================
// 6) final conv: out[b][o][m] = sum_c ao[b][m][c]*W[o][c] + bias[o]  (NCHW out)
// ============================================================================
__global__ __launch_bounds__(256) void projB_kernel(
    const float* __restrict__ X, const float* __restrict__ W,
    const float* __restrict__ bias, float* __restrict__ out)
{
    __shared__ float As[16][68];
    __shared__ float Ws[16][68];
    const int tid = threadIdx.x;
    const int b  = blockIdx.z;
    const int m0 = blockIdx.x * 64, o0 = blockIdx.y * 64;
    const float* Xb = X + (size_t)b * MTOK * CIN;

    const int mi = tid & 15;          // m = m0 + mi*4 .. +3
    const int oi = tid >> 4;          // o = o0 + oi*4 .. +3
    const int ar = tid >> 2, ac = (tid & 3) * 4;

    unsigned long long acc[4][2];
#pragma unroll
    for (int j = 0; j < 4; j++) { acc[j][0] = 0ull; acc[j][1] = 0ull; }

    for (int c0 = 0; c0 < CIN; c0 += 16) {
        __syncthreads();
        float4 xv = *(const float4*)&Xb[(size_t)(m0 + ar) * CIN + c0 + ac];
        As[ac + 0][ar] = xv.x; As[ac + 1][ar] = xv.y;
        As[ac + 2][ar] = xv.z; As[ac + 3][ar] = xv.w;
        float4 wv = *(const float4*)&W[(size_t)(o0 + ar) * CIN + c0 + ac];
        Ws[ac + 0][ar] = wv.x; Ws[ac + 1][ar] = wv.y;
        Ws[ac + 2][ar] = wv.z; Ws[ac + 3][ar] = wv.w;
        __syncthreads();
#pragma unroll
        for (int c = 0; c < 16; c++) {
            ulonglong2 mp = *(const ulonglong2*)&As[c][mi * 4];
#pragma unroll
            for (int j = 0; j < 4; j++) {
                unsigned long long wv2 = bcast2(Ws[c][oi * 4 + j]);
                ffma2(acc[j][0], mp.x, wv2);
                ffma2(acc[j][1], mp.y, wv2);
            }
        }
    }
#pragma unroll
    for (int j = 0; j < 4; j++) {
        float bv = bias[o0 + oi * 4 + j];
        float2 u0 = unpack2(acc[j][0]);
        float2 u1 = unpack2(acc[j][1]);
        *(float4*)&out[((size_t)b * CIN + o0 + oi * 4 + j) * MTOK + m0 + mi * 4] =
            make_float4(u0.x + bv, u0.y + bv, u1.x + bv, u1.y + bv);
    }
}

// ============================================================================
extern "C" void kernel_launch(void* const* d_in, const int* in_sizes, int n_in,
                              void* d_out, int out_size) {
    const float* content = (const float*)d_in[0];
    const float* style   = (const float*)d_in[1];
    const float* f_w = (const float*)d_in[2];
    const float* f_b = (const float*)d_in[3];
    const float* g_w = (const float*)d_in[4];
    const float* g_b = (const float*)d_in[5];
    const float* h_w = (const float*)d_in[6];
    const float* h_b = (const float*)d_in[7];
    const float* out_w = (const float*)d_in[8];
    const float* out_b = (const float*)d_in[9];
    float* out = (float*)d_out;

    float *styleR, *fP, *gP, *hP, *SP, *aoP;
    cudaGetSymbolAddress((void**)&styleR, d_styleR);
    cudaGetSymbolAddress((void**)&fP, d_f);
    cudaGetSymbolAddress((void**)&gP, d_g);
    cudaGetSymbolAddress((void**)&hP, d_h);
    cudaGetSymbolAddress((void**)&SP, d_S);
    cudaGetSymbolAddress((void**)&aoP, d_ao);

    resize_kernel<<<(4 * CIN * MTOK) / 256, 256>>>(style, styleR);
    proj_kernel<<<dim3(64, 1, 4), 256>>>(content, f_w, f_b, fP, CQK);
    proj_kernel<<<dim3(64, 1, 4), 256>>>(styleR, g_w, g_b, gP, CQK);
    proj_kernel<<<dim3(64, 8, 4), 256>>>(styleR, h_w, h_b, hP, CIN);
    logits_kernel<<<dim3(64, 64, 4), 256>>>(fP, gP, SP);
    softmax_kernel<<<4 * MTOK, 256>>>(SP);
    pv_kernel<<<dim3(32, 4, 4), 256>>>(SP, hP, aoP);
    projB_kernel<<<dim3(64, 8, 4), 256>>>(aoP, out_w, out_b, out);
}